// round 9
// baseline (speedup 1.0000x reference)
#include <cuda_runtime.h>
#include <cuda_bf16.h>

// GraphTrainNN: out[b] = prod_g  w2[g] * (w1[g]^2 + w0[g]*x[b,g]^2) / (w1[g]^2 + x[b,g]^2)
// B = 524288 rows, G = 127 genes. x: (B,G) fp32, w: (G,3) fp32.
//
// R9 = R8 (aligned float4 streaming, low/high split-product assembly)
//    + R4 (software pipelining via register ping-pong).
//  - 4-row group = 508 floats = 127 float4; warp loads slots lane+32j ->
//    4 aligned LDG.128, 512B contiguous per request.
//  - next group's loads issued BEFORE current group's compute, so the
//    compute + 5-level butterfly tail always has 2KB in flight per warp.
//  - gene of element (slot,c) = (4*lane + j + c) mod 127 -> 7 param pairs/lane.
//  - lane 31 handles row straddles via split points s={3,2,1,0}; others {4,..}.
//  - 1 division per row, butterfly with 4 interleaved chains, float4 store.

#define GG 127

__global__ __launch_bounds__(256, 4)
void hill_f4p_kernel(const float* __restrict__ x,
                     const float* __restrict__ w,
                     float* __restrict__ out,
                     int ngroups)
{
    const int lane   = threadIdx.x & 31;
    const int warp   = (blockIdx.x * blockDim.x + threadIdx.x) >> 5;
    const int nwarps = (gridDim.x * blockDim.x) >> 5;
    const bool l31   = (lane == 31);

    // ---- per-lane params: genes (4*lane + k) mod 127, k = 0..6 ----
    float p0[7], pn[7];
#pragma unroll
    for (int k = 0; k < 7; ++k) {
        int gene = 4 * lane + k;
        if (gene >= GG) gene -= GG;
        p0[k] = __ldg(&w[gene * 3 + 0]);
        const float kk = __ldg(&w[gene * 3 + 1]);
        pn[k] = kk * kk;
    }
    // prod of w2 over all genes (lane owns genes 4*lane+k, k<4, idx<127)
    float w2l = 1.0f;
#pragma unroll
    for (int k = 0; k < 4; ++k) {
        const int idx = 4 * lane + k;
        if (idx < GG) w2l *= __ldg(&w[idx * 3 + 2]);
    }
#pragma unroll
    for (int o = 16; o; o >>= 1)
        w2l *= __shfl_xor_sync(0xFFFFFFFFu, w2l, o);
    const float W2ALL = w2l;

    const float4* __restrict__ xg = reinterpret_cast<const float4*>(x);

    // ---- load one group's 4 aligned float4 ----
    auto load4 = [&](float4 (&v)[4], int grp) {
        const size_t base = (size_t)grp * GG;   // float4 units
#pragma unroll
        for (int j = 0; j < 4; ++j) {
            int slot = lane + 32 * j;
            if (slot > 126) slot = 126;          // lane31 j=3: dup, discarded
            v[j] = __ldg(xg + base + slot);
        }
    };

    // ---- compute one group (register-light low/high split fold) ----
    auto compute4 = [&](const float4 (&v)[4], int grp) {
        float num[4], den[4];
        float hn = 1.0f, hd = 1.0f;              // carry from previous slot
#pragma unroll
        for (int j = 0; j < 4; ++j) {
            const int s = l31 ? (3 - j) : 4;     // split point
            float ln = 1.0f, ld = 1.0f;
            float gn = 1.0f, gd = 1.0f;
            const float e[4] = { v[j].x, v[j].y, v[j].z, v[j].w };
#pragma unroll
            for (int c = 0; c < 4; ++c) {
                const int   k  = j + c;
                const float a  = e[c] * e[c];
                const float tn = fmaf(p0[k], a, pn[k]);  // wn + w0*x^2
                const float td = pn[k] + a;              // wn + x^2
                if (c < s) { ln *= tn; ld *= td; }
                else       { gn *= tn; gd *= td; }
            }
            num[j] = hn * ln;
            den[j] = hd * ld;
            hn = gn; hd = gd;
        }

        float rr[4];
#pragma unroll
        for (int r = 0; r < 4; ++r)
            rr[r] = __fdividef(num[r], den[r]);  // <=4 terms: safe range

#pragma unroll
        for (int o = 1; o <= 16; o <<= 1)
#pragma unroll
            for (int r = 0; r < 4; ++r)
                rr[r] *= __shfl_xor_sync(0xFFFFFFFFu, rr[r], o);

        if (lane == 0) {
            float4 o4;
            o4.x = W2ALL * rr[0];
            o4.y = W2ALL * rr[1];
            o4.z = W2ALL * rr[2];
            o4.w = W2ALL * rr[3];
            *reinterpret_cast<float4*>(out + grp * 4) = o4;
        }
    };

    // ---- pipelined group loop (ping-pong, no copies) ----
    int grp = warp;
    if (grp >= ngroups) return;

    float4 bufA[4], bufB[4];
    load4(bufA, grp);

    for (;;) {
        int nxt = grp + nwarps;
        if (nxt < ngroups) load4(bufB, nxt);     // prefetch while A computes
        compute4(bufA, grp);
        grp = nxt;
        if (grp >= ngroups) break;

        nxt = grp + nwarps;
        if (nxt < ngroups) load4(bufA, nxt);     // prefetch while B computes
        compute4(bufB, grp);
        grp = nxt;
        if (grp >= ngroups) break;
    }
}

extern "C" void kernel_launch(void* const* d_in, const int* in_sizes, int n_in,
                              void* d_out, int out_size)
{
    const float* x = (const float*)d_in[0];   // (B, G) fp32
    const float* w = (const float*)d_in[1];   // (G, 3) fp32
    float* out = (float*)d_out;               // (B, 1) fp32

    const int rows    = in_sizes[0] / GG;     // 524288
    const int ngroups = rows / 4;             // 131072

    const int threads = 256;
    const int blocks  = 2048;                 // 16384 warps -> 8 groups each
    hill_f4p_kernel<<<blocks, threads>>>(x, w, out, ngroups);
}

// round 10
// speedup vs baseline: 1.1778x; 1.1778x over previous
#include <cuda_runtime.h>
#include <cuda_bf16.h>

// GraphTrainNN: out[b] = prod_g  w2[g] * (w1[g]^2 + w0[g]*x[b,g]^2) / (w1[g]^2 + x[b,g]^2)
// B = 524288 rows, G = 127 genes. x: (B,G) fp32, w: (G,3) fp32.
//
// R10 = R8 (best: aligned float4 streaming, low/high split-product assembly,
//           48 regs, no pipeline) + STREAMING CACHE POLICY.
//  - x is a strictly read-once 266MB stream: __ldcs (evict-first L1+L2)
//    stops fill/evict churn from stealing LTS bandwidth; __stcs for out.
//  - 4-row group = 508 floats = 127 float4; warp loads slots lane+32j ->
//    4 aligned LDG.128, 512B contiguous per request.
//  - gene of element (slot,c) = (4*lane + j + c) mod 127 -> 7 param pairs/lane.
//  - lane 31 handles row straddles via split points s={3,2,1,0}; others {4}.
//  - 1 division per row, 5-level butterfly with 4 interleaved chains,
//    float4 output store. prod(w2) hoisted per warp.

#define GG 127

__global__ __launch_bounds__(256, 5)
void hill_f4cs_kernel(const float* __restrict__ x,
                      const float* __restrict__ w,
                      float* __restrict__ out,
                      int ngroups)
{
    const int lane   = threadIdx.x & 31;
    const int warp   = (blockIdx.x * blockDim.x + threadIdx.x) >> 5;
    const int nwarps = (gridDim.x * blockDim.x) >> 5;
    const bool l31   = (lane == 31);

    // ---- per-lane params: genes (4*lane + k) mod 127, k = 0..6 ----
    float p0[7], pn[7];
#pragma unroll
    for (int k = 0; k < 7; ++k) {
        int gene = 4 * lane + k;
        if (gene >= GG) gene -= GG;
        p0[k] = __ldg(&w[gene * 3 + 0]);
        const float kk = __ldg(&w[gene * 3 + 1]);
        pn[k] = kk * kk;
    }
    // prod of w2 over all genes (lane owns genes 4*lane+k, k<4, idx<127)
    float w2l = 1.0f;
#pragma unroll
    for (int k = 0; k < 4; ++k) {
        const int idx = 4 * lane + k;
        if (idx < GG) w2l *= __ldg(&w[idx * 3 + 2]);
    }
#pragma unroll
    for (int o = 16; o; o >>= 1)
        w2l *= __shfl_xor_sync(0xFFFFFFFFu, w2l, o);
    const float W2ALL = w2l;

    const float4* __restrict__ xg = reinterpret_cast<const float4*>(x);

    for (int grp = warp; grp < ngroups; grp += nwarps) {
        // ---- 4 aligned vector loads, streaming (evict-first) ----
        float4 v[4];
        const size_t base = (size_t)grp * GG;   // float4 units
#pragma unroll
        for (int j = 0; j < 4; ++j) {
            int slot = lane + 32 * j;
            if (slot > 126) slot = 126;          // lane31 j=3: dup, discarded
            v[j] = __ldcs(xg + base + slot);
        }

        // ---- low/high split products per slot, folded across rows ----
        float num[4], den[4];
        float hn = 1.0f, hd = 1.0f;              // carry from previous slot
#pragma unroll
        for (int j = 0; j < 4; ++j) {
            const int s = l31 ? (3 - j) : 4;     // split point for this slot
            float ln = 1.0f, ld = 1.0f;          // low part (this row)
            float gn = 1.0f, gd = 1.0f;          // high part (next row)
            const float e[4] = { v[j].x, v[j].y, v[j].z, v[j].w };
#pragma unroll
            for (int c = 0; c < 4; ++c) {
                const int   k  = j + c;
                const float a  = e[c] * e[c];
                const float tn = fmaf(p0[k], a, pn[k]);  // wn + w0*x^2
                const float td = pn[k] + a;              // wn + x^2
                if (c < s) { ln *= tn; ld *= td; }
                else       { gn *= tn; gd *= td; }
            }
            num[j] = hn * ln;
            den[j] = hd * ld;
            hn = gn; hd = gd;
        }

        // ---- 1 division per row (<=4 terms each: safe fp32 range) ----
        float rr[4];
#pragma unroll
        for (int r = 0; r < 4; ++r)
            rr[r] = __fdividef(num[r], den[r]);

        // ---- 32-lane product, 4 independent chains interleaved ----
#pragma unroll
        for (int o = 1; o <= 16; o <<= 1)
#pragma unroll
            for (int r = 0; r < 4; ++r)
                rr[r] *= __shfl_xor_sync(0xFFFFFFFFu, rr[r], o);

        if (lane == 0) {
            float4 o4;
            o4.x = W2ALL * rr[0];
            o4.y = W2ALL * rr[1];
            o4.z = W2ALL * rr[2];
            o4.w = W2ALL * rr[3];
            __stcs(reinterpret_cast<float4*>(out + grp * 4), o4);
        }
    }
}

extern "C" void kernel_launch(void* const* d_in, const int* in_sizes, int n_in,
                              void* d_out, int out_size)
{
    const float* x = (const float*)d_in[0];   // (B, G) fp32
    const float* w = (const float*)d_in[1];   // (G, 3) fp32
    float* out = (float*)d_out;               // (B, 1) fp32

    const int rows    = in_sizes[0] / GG;     // 524288
    const int ngroups = rows / 4;             // 131072

    const int threads = 256;
    const int blocks  = 2048;                 // 16384 warps -> 8 groups each
    hill_f4cs_kernel<<<blocks, threads>>>(x, w, out, ngroups);
}